// round 17
// baseline (speedup 1.0000x reference)
#include <cuda_runtime.h>
#include <cuda_bf16.h>
#include <cstdint>

#define NN 50000
#define EE 800000
#define FF 128
#define ELLW 64
#define NPAD (NN + 128)      // pad rows so GEMM tiles can over-read safely

// ---------------- device scratch ----------------
__device__ float g_deg[NN];
__device__ int   g_cursor[NN];
__device__ __align__(16) int2 g_cs[(size_t)NN * ELLW];   // ELL: {src, norm-bits}
__device__ float g_xw[(size_t)NPAD * FF];                // GEMM output (fp32)
__device__ __nv_bfloat16 g_ahi[(size_t)NPAD * FF];       // GEMM input hi
__device__ __nv_bfloat16 g_alo[(size_t)NPAD * FF];       // GEMM input lo
__device__ float g_xw2[(size_t)NN * 2];
__device__ __nv_bfloat16 g_whi[7 * FF * FF];   // [layer][n][k] K-major
__device__ __nv_bfloat16 g_wlo[7 * FF * FF];

// ---------------- prep ----------------
__global__ void k_prep0(const float* __restrict__ W1, const float* __restrict__ Wmid,
                        __nv_bfloat16* __restrict__ whi, __nv_bfloat16* __restrict__ wlo,
                        float* __restrict__ deg, int* __restrict__ cursor) {
    int idx = blockIdx.x * blockDim.x + threadIdx.x;
    if (idx < NN) { deg[idx] = 1.0f; cursor[idx] = 0; }
    if (idx < 7 * FF * FF) {
        int l = idx / (FF * FF);
        int r = idx % (FF * FF);
        int k = r >> 7;
        int n = r & 127;
        float w = (l == 0) ? W1[k * FF + n] : Wmid[(size_t)(l - 1) * FF * FF + k * FF + n];
        __nv_bfloat16 hi = __float2bfloat16_rn(w);
        __nv_bfloat16 lo = __float2bfloat16_rn(w - __bfloat162float(hi));
        whi[(size_t)l * FF * FF + n * FF + k] = hi;
        wlo[(size_t)l * FF * FF + n * FF + k] = lo;
    }
}

__global__ void k_edge_prep(const int* __restrict__ ei,
                            const float* __restrict__ ew,
                            float* __restrict__ deg) {
    int e = blockIdx.x * blockDim.x + threadIdx.x;
    if (e >= EE) return;
    atomicAdd(&deg[ei[EE + e]], ew[e]);
}

__global__ void k_fill(const int* __restrict__ ei, const float* __restrict__ ew,
                       const float* __restrict__ deg,
                       int* __restrict__ cursor, int2* __restrict__ cs) {
    int e = blockIdx.x * blockDim.x + threadIdx.x;
    if (e >= EE) return;
    int s = ei[e];
    int d = ei[EE + e];
    float nrm = rsqrtf(deg[s]) * ew[e] * rsqrtf(deg[d]);
    int p = atomicAdd(&cursor[d], 1);
    if (p < ELLW)
        cs[((size_t)d << 6) + p] = make_int2(s, __float_as_int(nrm));
}

// split x (no relu) into bf16 hi/lo for the layer-1 GEMM
__global__ void k_xsplit(const float* __restrict__ x,
                         __nv_bfloat16* __restrict__ hi, __nv_bfloat16* __restrict__ lo) {
    int i = blockIdx.x * blockDim.x + threadIdx.x;
    if (i >= NN * FF / 4) return;
    float4 v = ((const float4*)x)[i];
    __nv_bfloat16 h0 = __float2bfloat16_rn(v.x);
    __nv_bfloat16 h1 = __float2bfloat16_rn(v.y);
    __nv_bfloat16 h2 = __float2bfloat16_rn(v.z);
    __nv_bfloat16 h3 = __float2bfloat16_rn(v.w);
    __nv_bfloat16 l0 = __float2bfloat16_rn(v.x - __bfloat162float(h0));
    __nv_bfloat16 l1 = __float2bfloat16_rn(v.y - __bfloat162float(h1));
    __nv_bfloat16 l2 = __float2bfloat16_rn(v.z - __bfloat162float(h2));
    __nv_bfloat16 l3 = __float2bfloat16_rn(v.w - __bfloat162float(h3));
    __nv_bfloat162 hh0 = __halves2bfloat162(h0, h1);
    __nv_bfloat162 hh1 = __halves2bfloat162(h2, h3);
    __nv_bfloat162 ll0 = __halves2bfloat162(l0, l1);
    __nv_bfloat162 ll1 = __halves2bfloat162(l2, l3);
    ((uint2*)hi)[i] = make_uint2(*(uint32_t*)&hh0, *(uint32_t*)&hh1);
    ((uint2*)lo)[i] = make_uint2(*(uint32_t*)&ll0, *(uint32_t*)&ll1);
}

// ---------------- cp.async + ldmatrix double-buffered GEMM ----------------
#define SSTR 40
#define CHUNK_ELEMS (128 * SSTR)           // bf16 elems per section
#define CHUNK_BYTES (CHUNK_ELEMS * 2)      // 10240
#define BUF_BYTES (4 * CHUNK_BYTES)        // 40960: sections Ahi,Alo,Whi,Wlo
#define GEMM_SMEM (2 * BUF_BYTES)          // 81920

__device__ __forceinline__ void mma16816(float* d, const uint32_t* a, const uint32_t* b) {
    asm volatile(
        "mma.sync.aligned.m16n8k16.row.col.f32.bf16.bf16.f32 "
        "{%0,%1,%2,%3}, {%4,%5,%6,%7}, {%8,%9}, {%0,%1,%2,%3};"
        : "+f"(d[0]), "+f"(d[1]), "+f"(d[2]), "+f"(d[3])
        : "r"(a[0]), "r"(a[1]), "r"(a[2]), "r"(a[3]), "r"(b[0]), "r"(b[1]));
}

__device__ __forceinline__ void ldsm4(uint32_t* r, uint32_t addr) {
    asm volatile("ldmatrix.sync.aligned.m8n8.x4.shared.b16 {%0,%1,%2,%3}, [%4];"
                 : "=r"(r[0]), "=r"(r[1]), "=r"(r[2]), "=r"(r[3]) : "r"(addr));
}

__device__ __forceinline__ void cpa16(uint32_t dst, const void* src) {
    asm volatile("cp.async.cg.shared.global [%0], [%1], 16;" :: "r"(dst), "l"(src));
}

__global__ void __launch_bounds__(256, 2) k_gemm_fast(
    const __nv_bfloat16* __restrict__ Ahi, const __nv_bfloat16* __restrict__ Alo,
    const __nv_bfloat16* __restrict__ whi, const __nv_bfloat16* __restrict__ wlo,
    float* __restrict__ xw, int M) {
    extern __shared__ __nv_bfloat16 smraw[];
    uint32_t smBase = (uint32_t)__cvta_generic_to_shared(smraw);

    int tid = threadIdx.x;
    int wid = tid >> 5;
    int lane = tid & 31;
    int g = lane >> 2;
    int tg = lane & 3;
    int warp_m = wid & 1;
    int warp_n = wid >> 1;
    int row0 = blockIdx.x * 128;

    // cp.async mapping: 8 granules/thread; j>>1 = section, row = (j&1)*64 + tid/4, q = tid&3
    int cp_row = tid >> 2;
    int cp_q = tid & 3;

    // ldmatrix lane patterns (same as proven R16 kernel)
    int a_row  = warp_m * 64 + (lane & 15);
    int a_colx = (lane >> 4) << 3;
    int b_row  = warp_n * 32 + ((lane >> 4) << 3) + (lane & 7);
    int b_colx = ((lane >> 3) & 1) << 3;

    float acc[4][4][4];
#pragma unroll
    for (int mf = 0; mf < 4; mf++)
#pragma unroll
        for (int nf = 0; nf < 4; nf++)
#pragma unroll
            for (int r = 0; r < 4; r++) acc[mf][nf][r] = 0.0f;

    // issue one chunk's cp.asyncs into buffer `buf`
    auto issue = [&](int k0, int buf) {
        uint32_t dbase = smBase + (uint32_t)(buf * BUF_BYTES);
#pragma unroll
        for (int j = 0; j < 8; j++) {
            int sect = j >> 1;
            int row = ((j & 1) << 6) + cp_row;
            uint32_t dst = dbase + (uint32_t)(sect * CHUNK_BYTES + (row * SSTR + cp_q * 8) * 2);
            const __nv_bfloat16* src;
            if (sect == 0)      src = Ahi + (size_t)(row0 + row) * FF + k0 + cp_q * 8;
            else if (sect == 1) src = Alo + (size_t)(row0 + row) * FF + k0 + cp_q * 8;
            else if (sect == 2) src = whi + (size_t)row * FF + k0 + cp_q * 8;
            else                src = wlo + (size_t)row * FF + k0 + cp_q * 8;
            cpa16(dst, src);
        }
        asm volatile("cp.async.commit_group;");
    };

    issue(0, 0);
    for (int c = 0; c < 4; c++) {
        if (c < 3) {
            issue((c + 1) * 32, (c + 1) & 1);
            asm volatile("cp.async.wait_group 1;");
        } else {
            asm volatile("cp.async.wait_group 0;");
        }
        __syncthreads();

        uint32_t bb = smBase + (uint32_t)((c & 1) * BUF_BYTES);
#pragma unroll
        for (int chain = 0; chain < 3; chain++) {
            uint32_t abase = bb + (chain == 2 ? CHUNK_BYTES : 0);           // Ahi or Alo
            uint32_t bbase = bb + (chain == 1 ? 3 : 2) * CHUNK_BYTES;       // Whi or Wlo
#pragma unroll
            for (int ks = 0; ks < 2; ks++) {
                int kb = ks * 16;
                uint32_t afr[4][4];
#pragma unroll
                for (int mf = 0; mf < 4; mf++)
                    ldsm4(afr[mf], abase +
                          (uint32_t)(((a_row + mf * 16) * SSTR + kb + a_colx) * 2));
                uint32_t bfr[2][4];
#pragma unroll
                for (int p = 0; p < 2; p++)
                    ldsm4(bfr[p], bbase +
                          (uint32_t)(((b_row + p * 16) * SSTR + kb + b_colx) * 2));
#pragma unroll
                for (int mf = 0; mf < 4; mf++)
#pragma unroll
                    for (int p = 0; p < 2; p++) {
                        mma16816(acc[mf][2 * p],     afr[mf], &bfr[p][0]);
                        mma16816(acc[mf][2 * p + 1], afr[mf], &bfr[p][2]);
                    }
            }
        }
        __syncthreads();
    }

#pragma unroll
    for (int mf = 0; mf < 4; mf++) {
        int r_up = row0 + warp_m * 64 + mf * 16 + g;
        int r_dn = r_up + 8;
#pragma unroll
        for (int nf = 0; nf < 4; nf++) {
            int col = warp_n * 32 + nf * 8 + tg * 2;
            if (r_up < M)
                *(float2*)(xw + (size_t)r_up * FF + col) =
                    make_float2(acc[mf][nf][0], acc[mf][nf][1]);
            if (r_dn < M)
                *(float2*)(xw + (size_t)r_dn * FF + col) =
                    make_float2(acc[mf][nf][2], acc[mf][nf][3]);
        }
    }
}

// ---------------- ELL aggregation (+relu +bf16 split epilogue) ------------
__device__ __forceinline__ float4 ldcg4(const float* p) {
    float4 v;
    asm("ld.global.cg.v4.f32 {%0,%1,%2,%3}, [%4];"
        : "=f"(v.x), "=f"(v.y), "=f"(v.z), "=f"(v.w) : "l"(p));
    return v;
}

__global__ void __launch_bounds__(256) k_agg128(
    const int* __restrict__ cnt, const int2* __restrict__ cs,
    const float* __restrict__ xw,
    const float* __restrict__ bias, const float* __restrict__ deg,
    __nv_bfloat16* __restrict__ ohi, __nv_bfloat16* __restrict__ olo) {
    int v = (blockIdx.x * blockDim.x + threadIdx.x) >> 5;
    if (v >= NN) return;
    int lane = threadIdx.x & 31;

    float4 acc = ldcg4(xw + (size_t)v * FF + lane * 4);
    float dv = rsqrtf(deg[v]);
    float d2 = dv * dv;
    float4 b = *(const float4*)(bias + lane * 4);
    acc.x = b.x + d2 * acc.x;
    acc.y = b.y + d2 * acc.y;
    acc.z = b.z + d2 * acc.z;
    acc.w = b.w + d2 * acc.w;

    int n = min(cnt[v], ELLW);
    const int2* row = cs + ((size_t)v << 6);
    int i = 0;
    for (; i + 3 < n; i += 4) {
        int2 e0 = row[i],     e1 = row[i + 1];
        int2 e2 = row[i + 2], e3 = row[i + 3];
        float4 v0 = ldcg4(xw + (size_t)e0.x * FF + lane * 4);
        float4 v1 = ldcg4(xw + (size_t)e1.x * FF + lane * 4);
        float4 v2 = ldcg4(xw + (size_t)e2.x * FF + lane * 4);
        float4 v3 = ldcg4(xw + (size_t)e3.x * FF + lane * 4);
        float w0 = __int_as_float(e0.y), w1 = __int_as_float(e1.y);
        float w2 = __int_as_float(e2.y), w3 = __int_as_float(e3.y);
        acc.x += w0 * v0.x; acc.y += w0 * v0.y; acc.z += w0 * v0.z; acc.w += w0 * v0.w;
        acc.x += w1 * v1.x; acc.y += w1 * v1.y; acc.z += w1 * v1.z; acc.w += w1 * v1.w;
        acc.x += w2 * v2.x; acc.y += w2 * v2.y; acc.z += w2 * v2.z; acc.w += w2 * v2.w;
        acc.x += w3 * v3.x; acc.y += w3 * v3.y; acc.z += w3 * v3.z; acc.w += w3 * v3.w;
    }
    for (; i < n; i++) {
        int2 e0 = row[i];
        float w0 = __int_as_float(e0.y);
        float4 v0 = ldcg4(xw + (size_t)e0.x * FF + lane * 4);
        acc.x += w0 * v0.x; acc.y += w0 * v0.y;
        acc.z += w0 * v0.z; acc.w += w0 * v0.w;
    }

    // relu + bf16 split (same fp32 values the GEMM used to see)
    acc.x = fmaxf(acc.x, 0.f); acc.y = fmaxf(acc.y, 0.f);
    acc.z = fmaxf(acc.z, 0.f); acc.w = fmaxf(acc.w, 0.f);
    __nv_bfloat16 h0 = __float2bfloat16_rn(acc.x);
    __nv_bfloat16 h1 = __float2bfloat16_rn(acc.y);
    __nv_bfloat16 h2 = __float2bfloat16_rn(acc.z);
    __nv_bfloat16 h3 = __float2bfloat16_rn(acc.w);
    __nv_bfloat16 l0 = __float2bfloat16_rn(acc.x - __bfloat162float(h0));
    __nv_bfloat16 l1 = __float2bfloat16_rn(acc.y - __bfloat162float(h1));
    __nv_bfloat16 l2 = __float2bfloat16_rn(acc.z - __bfloat162float(h2));
    __nv_bfloat16 l3 = __float2bfloat16_rn(acc.w - __bfloat162float(h3));
    __nv_bfloat162 hh0 = __halves2bfloat162(h0, h1);
    __nv_bfloat162 hh1 = __halves2bfloat162(h2, h3);
    __nv_bfloat162 ll0 = __halves2bfloat162(l0, l1);
    __nv_bfloat162 ll1 = __halves2bfloat162(l2, l3);
    *(uint2*)(ohi + (size_t)v * FF + lane * 4) = make_uint2(*(uint32_t*)&hh0, *(uint32_t*)&hh1);
    *(uint2*)(olo + (size_t)v * FF + lane * 4) = make_uint2(*(uint32_t*)&ll0, *(uint32_t*)&ll1);
}

// ---------------- layer 8: skinny GEMM (128 -> 2), bf16 hi/lo input --------
__global__ void __launch_bounds__(256) k_gemm2(
    const __nv_bfloat16* __restrict__ Ahi, const __nv_bfloat16* __restrict__ Alo,
    const float* __restrict__ W8, float* __restrict__ xw2, int M) {
    __shared__ float Ws[256];
    int tid = threadIdx.x;
    Ws[tid] = W8[tid];
    __syncthreads();

    int w = (blockIdx.x * blockDim.x + tid) >> 5;
    if (w >= M) return;
    int lane = tid & 31;

    uint2 hp = *(const uint2*)(Ahi + (size_t)w * FF + lane * 4);
    uint2 lp = *(const uint2*)(Alo + (size_t)w * FF + lane * 4);
    __nv_bfloat162 h01 = *(__nv_bfloat162*)&hp.x;
    __nv_bfloat162 h23 = *(__nv_bfloat162*)&hp.y;
    __nv_bfloat162 l01 = *(__nv_bfloat162*)&lp.x;
    __nv_bfloat162 l23 = *(__nv_bfloat162*)&lp.y;
    float a0 = __bfloat162float(__low2bfloat16(h01))  + __bfloat162float(__low2bfloat16(l01));
    float a1 = __bfloat162float(__high2bfloat16(h01)) + __bfloat162float(__high2bfloat16(l01));
    float a2 = __bfloat162float(__low2bfloat16(h23))  + __bfloat162float(__low2bfloat16(l23));
    float a3 = __bfloat162float(__high2bfloat16(h23)) + __bfloat162float(__high2bfloat16(l23));

    int k = lane * 4;
    float s0 = a0 * Ws[(k + 0) * 2] + a1 * Ws[(k + 1) * 2] +
               a2 * Ws[(k + 2) * 2] + a3 * Ws[(k + 3) * 2];
    float s1 = a0 * Ws[(k + 0) * 2 + 1] + a1 * Ws[(k + 1) * 2 + 1] +
               a2 * Ws[(k + 2) * 2 + 1] + a3 * Ws[(k + 3) * 2 + 1];
#pragma unroll
    for (int off = 16; off; off >>= 1) {
        s0 += __shfl_xor_sync(0xFFFFFFFFu, s0, off);
        s1 += __shfl_xor_sync(0xFFFFFFFFu, s1, off);
    }
    if (lane == 0) {
        xw2[(size_t)w * 2]     = s0;
        xw2[(size_t)w * 2 + 1] = s1;
    }
}

__global__ void __launch_bounds__(256) k_agg2(
    const int* __restrict__ cnt, const int2* __restrict__ cs,
    const float* __restrict__ xw2,
    const float* __restrict__ b8, const float* __restrict__ deg,
    float* __restrict__ outb) {
    int v = blockIdx.x * blockDim.x + threadIdx.x;
    if (v >= NN) return;
    float2 a = *(const float2*)(xw2 + (size_t)v * 2);
    float dv = rsqrtf(deg[v]);
    float d2 = dv * dv;
    float s0 = b8[0] + d2 * a.x;
    float s1 = b8[1] + d2 * a.y;
    int n = min(cnt[v], ELLW);
    const int2* row = cs + ((size_t)v << 6);
    for (int i = 0; i < n; i++) {
        int2 e = row[i];
        float w = __int_as_float(e.y);
        float2 xv = *(const float2*)(xw2 + (size_t)e.x * 2);
        s0 += w * xv.x;
        s1 += w * xv.y;
    }
    outb[(size_t)v * 2]     = s0;
    outb[(size_t)v * 2 + 1] = s1;
}

// ---------------- launcher ----------------
extern "C" void kernel_launch(void* const* d_in, const int* in_sizes, int n_in,
                              void* d_out, int out_size) {
    const float* x    = (const float*)d_in[0];
    const int*   ei   = (const int*)d_in[1];
    const float* ea   = (const float*)d_in[2];
    const float* W1   = (const float*)d_in[3];
    const float* b1   = (const float*)d_in[4];
    const float* Wmid = (const float*)d_in[5];
    const float* bmid = (const float*)d_in[6];
    const float* W8   = (const float*)d_in[7];
    const float* b8   = (const float*)d_in[8];
    float* out = (float*)d_out;

    float *deg, *xw, *xw2;
    int *cursor;
    int2* cs;
    __nv_bfloat16 *whi, *wlo, *ahi, *alo;
    cudaGetSymbolAddress((void**)&deg,    g_deg);
    cudaGetSymbolAddress((void**)&cursor, g_cursor);
    cudaGetSymbolAddress((void**)&cs,     g_cs);
    cudaGetSymbolAddress((void**)&xw,     g_xw);
    cudaGetSymbolAddress((void**)&ahi,    g_ahi);
    cudaGetSymbolAddress((void**)&alo,    g_alo);
    cudaGetSymbolAddress((void**)&xw2,    g_xw2);
    cudaGetSymbolAddress((void**)&whi,    g_whi);
    cudaGetSymbolAddress((void**)&wlo,    g_wlo);

    cudaFuncSetAttribute(k_gemm_fast, cudaFuncAttributeMaxDynamicSharedMemorySize, GEMM_SMEM);

    const int TB = 256;
    const int NB_N = (NN + TB - 1) / TB;
    const int NB_E = (EE + TB - 1) / TB;

    // prep
    k_prep0<<<(7 * FF * FF + TB - 1) / TB, TB>>>(W1, Wmid, whi, wlo, deg, cursor);
    k_edge_prep<<<NB_E, TB>>>(ei, ea, deg);
    k_fill<<<NB_E, TB>>>(ei, ea, deg, cursor, cs);
    k_xsplit<<<(NN * FF / 4 + TB - 1) / TB, TB>>>(x, ahi, alo);

    const int GEMM_BLOCKS = (NN + 127) / 128;
    const int AGG_BLOCKS  = (int)(((long long)NN * 32 + TB - 1) / TB);

    // layers 1..7: gemm_fast -> agg (relu + bf16 split back into ahi/alo)
    for (int l = 0; l < 7; l++) {
        const __nv_bfloat16* wh = whi + (size_t)l * FF * FF;
        const __nv_bfloat16* wl = wlo + (size_t)l * FF * FF;
        const float* b = (l == 0) ? b1 : bmid + (size_t)(l - 1) * FF;
        k_gemm_fast<<<GEMM_BLOCKS, TB, GEMM_SMEM>>>(ahi, alo, wh, wl, xw, NN);
        k_agg128<<<AGG_BLOCKS, TB>>>(cursor, cs, xw, b, deg, ahi, alo);
    }

    // layer 8
    k_gemm2<<<(int)(((long long)NN * 32 + TB - 1) / TB), TB>>>(ahi, alo, W8, xw2, NN);
    k_agg2<<<NB_N, TB>>>(cursor, cs, xw2, b8, deg, out);
}